// round 14
// baseline (speedup 1.0000x reference)
#include <cuda_runtime.h>
#include <math.h>
#include <stdint.h>

#if defined(__CUDA_ARCH__) && defined(__CUDA_ARCH_FEAT_SM103_ALL)
#define USE_TC 1
#else
#define USE_TC 0
#endif

#define NTOK 4096
#define CDIM 2048
#define FDIM 1024
#define NEXP 8
#define RPAD (2*NTOK + NEXP*128)   // 8704 padded permuted rows

// ---------------- device scratch ----------------
__device__ int   g_te[NTOK*2];
__device__ float g_tp[NTOK*2];
__device__ int   g_cnt[NEXP];
__device__ int   g_base[NEXP];
__device__ int   g_tok[RPAD];
__device__ float g_w[RPAD];
__device__ int   g_pos[NTOK*2];
__device__ float g_xt[(size_t)NTOK * CDIM];        // tf32-rounded x
__device__ float g_H[(size_t)RPAD * FDIM];
__device__ float g_O[(size_t)RPAD * CDIM];
__device__ float g_w1t[(size_t)NEXP*FDIM*CDIM];    // [E][F][C] K-major tf32
__device__ float g_w3t[(size_t)NEXP*FDIM*CDIM];
__device__ float g_w2t[(size_t)NEXP*CDIM*FDIM];    // [E][C][F] K-major tf32

// ---------------- helpers ----------------
__device__ __forceinline__ uint32_t smem_u32(const void* p) {
    uint32_t a;
    asm("{ .reg .u64 t; cvta.to.shared.u64 t, %1; cvt.u32.u64 %0, t; }" : "=r"(a) : "l"(p));
    return a;
}
__device__ __forceinline__ float to_tf32(float x) {
    float r; asm("cvt.rna.tf32.f32 %0, %1;" : "=f"(r) : "f"(x)); return r;
}

#if USE_TC
__device__ __forceinline__ uint32_t elect_one() {
    uint32_t p;
    asm volatile("{ .reg .pred p; elect.sync _|p, 0xFFFFFFFF; selp.b32 %0, 1, 0, p; }" : "=r"(p));
    return p;
}
__device__ __forceinline__ float fast_tanh(float x) {
    float r; asm("tanh.approx.f32 %0, %1;" : "=f"(r) : "f"(x)); return r;
}
#define MBAR_INIT(a, c) asm volatile("mbarrier.init.shared.b64 [%0], %1;" :: "r"(a), "r"(c) : "memory")
__device__ __forceinline__ void mbar_wait(uint32_t addr, uint32_t parity) {
    asm volatile(
        "{\n\t.reg .pred P;\n\t"
        "W_%=:\n\t"
        "mbarrier.try_wait.parity.acquire.cta.shared::cta.b64 P, [%0], %1, 0x989680;\n\t"
        "@P bra D_%=;\n\t"
        "bra W_%=;\n\t"
        "D_%=:\n\t}"
        :: "r"(addr), "r"(parity) : "memory");
}
#define TC_ALLOC(sa, n)   asm volatile("tcgen05.alloc.cta_group::1.sync.aligned.shared::cta.b32 [%0], %1;" :: "r"(sa), "r"(n) : "memory")
#define TC_DEALLOC(t, n)  asm volatile("tcgen05.dealloc.cta_group::1.sync.aligned.b32 %0, %1;" :: "r"(t), "r"(n))
#define TC_RELINQ()       asm volatile("tcgen05.relinquish_alloc_permit.cta_group::1.sync.aligned;")
#define TC_COMMIT(mb)     asm volatile("tcgen05.commit.cta_group::1.mbarrier::arrive::one.shared::cluster.b64 [%0];" :: "r"(mb) : "memory")
#define TC_FENCE_AFTER()  asm volatile("tcgen05.fence::after_thread_sync;" ::: "memory")
#define TC_FENCE_BEFORE() asm volatile("tcgen05.fence::before_thread_sync;" ::: "memory")
#define TC_WAIT_LD()      asm volatile("tcgen05.wait::ld.sync.aligned;" ::: "memory")
#define FENCE_ASYNC()     asm volatile("fence.proxy.async.shared::cta;" ::: "memory")

#define CP_ASYNC16(sm, gm) asm volatile("cp.async.cg.shared.global [%0], [%1], 16;" :: "r"(sm), "l"(gm) : "memory")
// .noinc is load-bearing: default form increments pending count first (net
// zero progress) and the barrier never flips — R13 deadlocked on exactly this.
#define CP_MBAR_ARRIVE(mb) asm volatile("cp.async.mbarrier.arrive.noinc.shared::cta.b64 [%0];" :: "r"(mb) : "memory")

__device__ __forceinline__ void mma_tf32_ss(uint32_t d, uint64_t a, uint64_t b,
                                            uint32_t idesc, uint32_t acc) {
    asm volatile(
        "{\n\t.reg .pred p;\n\tsetp.ne.u32 p, %5, 0;\n\t"
        "tcgen05.mma.cta_group::1.kind::tf32 [%0], %1, %2, %3, {%4, %4, %4, %4}, p;\n\t}"
        :: "r"(d), "l"(a), "l"(b), "r"(idesc), "r"(0u), "r"(acc) : "memory");
}

#define TMEM_LD32(r, a) \
    asm volatile("tcgen05.ld.sync.aligned.32x32b.x32.b32 " \
        "{%0,%1,%2,%3,%4,%5,%6,%7,%8,%9,%10,%11,%12,%13,%14,%15," \
        "%16,%17,%18,%19,%20,%21,%22,%23,%24,%25,%26,%27,%28,%29,%30,%31}, [%32];" \
        : "=r"((r)[0]),"=r"((r)[1]),"=r"((r)[2]),"=r"((r)[3]),"=r"((r)[4]),"=r"((r)[5]),"=r"((r)[6]),"=r"((r)[7]), \
          "=r"((r)[8]),"=r"((r)[9]),"=r"((r)[10]),"=r"((r)[11]),"=r"((r)[12]),"=r"((r)[13]),"=r"((r)[14]),"=r"((r)[15]), \
          "=r"((r)[16]),"=r"((r)[17]),"=r"((r)[18]),"=r"((r)[19]),"=r"((r)[20]),"=r"((r)[21]),"=r"((r)[22]),"=r"((r)[23]), \
          "=r"((r)[24]),"=r"((r)[25]),"=r"((r)[26]),"=r"((r)[27]),"=r"((r)[28]),"=r"((r)[29]),"=r"((r)[30]),"=r"((r)[31]) \
        : "r"(a))

static __device__ __forceinline__ uint64_t make_desc(uint32_t addr) {
    const uint64_t base =
        (uint64_t(2) << 61) | (uint64_t(1) << 46) | (uint64_t(64) << 32) | (uint64_t(1) << 16);
    return base | ((uint64_t)(addr >> 4) & 0x3FFF);
}
#define SWZ(o) ((o) ^ (((o) >> 3) & 0x70))
#define IDESC_N128 (0x10u | (2u<<7) | (2u<<10) | ((128u/8u)<<17) | ((128u/16u)<<24))
#define IDESC_N256 (0x10u | (2u<<7) | (2u<<10) | ((256u/8u)<<17) | ((128u/16u)<<24))
#endif // USE_TC

// ---------------- prep: transposes (y=0..2) + xt/init (y=3) ----------------
__global__ __launch_bounds__(256) void prep_kernel(
    const float4* __restrict__ x4,
    const float* __restrict__ w1, const float* __restrict__ w3,
    const float* __restrict__ w2) {
    int which = blockIdx.y;
    if (which == 3) {
        int i = blockIdx.x * blockDim.x + threadIdx.x;
        float4 v = x4[i];
        v.x = to_tf32(v.x); v.y = to_tf32(v.y); v.z = to_tf32(v.z); v.w = to_tf32(v.w);
        ((float4*)g_xt)[i] = v;
        if (i < RPAD) g_tok[i] = -1;
        if (i < NEXP) g_cnt[i] = 0;
        return;
    }
    if (blockIdx.x >= 4096) return;
    __shared__ float ts[32][129];
    const float* in;
    float* out;
    int R, Cc;
    if (which == 0)      { in = w1; out = g_w1t; R = CDIM; Cc = FDIM; }
    else if (which == 1) { in = w3; out = g_w3t; R = CDIM; Cc = FDIM; }
    else                 { in = w2; out = g_w2t; R = FDIM; Cc = CDIM; }
    int nx = Cc / 128;
    int e = blockIdx.x / (nx * (R / 32));
    int rem = blockIdx.x % (nx * (R / 32));
    int cx = rem % nx, rx = rem / nx;
    size_t eoff = (size_t)e * R * Cc;
    int c0 = cx * 128;
    int r0 = rx * 32;
    int tx = threadIdx.x & 31, ty = threadIdx.x >> 5;
    #pragma unroll
    for (int j = ty; j < 32; j += 8) {
        float4 v = *(const float4*)(in + eoff + (size_t)(r0 + j) * Cc + c0 + tx * 4);
        ts[j][tx*4+0] = to_tf32(v.x);
        ts[j][tx*4+1] = to_tf32(v.y);
        ts[j][tx*4+2] = to_tf32(v.z);
        ts[j][tx*4+3] = to_tf32(v.w);
    }
    __syncthreads();
    int t = threadIdx.x;
    #pragma unroll
    for (int i = 0; i < 4; i++) {
        int idx = t + i * 256;
        int oc = idx >> 3;
        int q4 = idx & 7;
        float4 v;
        v.x = ts[q4*4+0][oc];
        v.y = ts[q4*4+1][oc];
        v.z = ts[q4*4+2][oc];
        v.w = ts[q4*4+3][oc];
        *(float4*)(out + eoff + (size_t)(c0 + oc) * R + r0 + q4 * 4) = v;
    }
}

// ---------------- router ----------------
__global__ void router_kernel(const float* __restrict__ x, const float* __restrict__ wr) {
    __shared__ float xs[CDIM];
    __shared__ float lg[NEXP];
    int t = blockIdx.x;
    const float4* xrow = (const float4*)(x + (size_t)t * CDIM);
    for (int i = threadIdx.x; i < CDIM / 4; i += blockDim.x)
        ((float4*)xs)[i] = xrow[i];
    __syncthreads();
    int warp = threadIdx.x >> 5, lane = threadIdx.x & 31;
    float s = 0.f;
    #pragma unroll 8
    for (int c = lane; c < CDIM; c += 32) s += xs[c] * wr[c * NEXP + warp];
    #pragma unroll
    for (int o = 16; o > 0; o >>= 1) s += __shfl_xor_sync(0xFFFFFFFFu, s, o);
    if (lane == 0) lg[warp] = s;
    __syncthreads();
    if (threadIdx.x == 0) {
        int i0 = 0; float v0 = lg[0];
        #pragma unroll
        for (int e = 1; e < NEXP; e++) if (lg[e] > v0) { v0 = lg[e]; i0 = e; }
        int i1 = -1; float v1 = -INFINITY;
        #pragma unroll
        for (int e = 0; e < NEXP; e++) if (e != i0 && lg[e] > v1) { v1 = lg[e]; i1 = e; }
        float e1 = __expf(v1 - v0);
        float inv = 1.f / (1.f + e1);
        g_te[t*2+0] = i0; g_tp[t*2+0] = inv;
        g_te[t*2+1] = i1; g_tp[t*2+1] = e1 * inv;
        atomicAdd(&g_cnt[i0], 1);
        atomicAdd(&g_cnt[i1], 1);
    }
}

// ---------------- offsets + scatter fused (single block) ----------------
__global__ __launch_bounds__(1024) void offsets_scatter_kernel() {
    __shared__ int s_fill[NEXP];
    if (threadIdx.x == 0) {
        int b = 0;
        #pragma unroll
        for (int e = 0; e < NEXP; e++) {
            g_base[e] = b;
            b += ((g_cnt[e] + 127) >> 7) << 7;
        }
    }
    if (threadIdx.x < NEXP) s_fill[threadIdx.x] = 0;
    __syncthreads();
    for (int t = threadIdx.x; t < NTOK; t += 1024) {
        #pragma unroll
        for (int k = 0; k < 2; k++) {
            int e = g_te[t*2+k];
            int pos = g_base[e] + atomicAdd(&s_fill[e], 1);
            g_tok[pos] = t;
            g_w[pos] = g_tp[t*2+k];
            g_pos[t*2+k] = pos;
        }
    }
}

// ======== GEMM1: warp-specialized, M=128 N=128/CTA, 2 CTAs/SM, fused SwiGLU ========
// ctrl: +0 tmem, +16 full0(224), +24 full1(224), +32 done0(1), +40 done1(1), +48 fin(1)
#define G1_A(s)  ((s)*16384)
#define G1_B1(s) (32768 + (s)*16384)
#define G1_B2(s) (65536 + (s)*16384)
#define G1_CTRL  98304
#define G1_SMEM  (98304 + 64 + 1024 + 1024)

__global__ __launch_bounds__(256, 2) void gemm1_kernel() {
    int e = blockIdx.z;
    int cnt = g_cnt[e];
    int rt = blockIdx.x;
    if (rt * 128 >= cnt) return;
    int r0 = g_base[e] + rt * 128;
    int f0 = blockIdx.y * 128;
    int t = threadIdx.x;
    const float* b1base = g_w1t + ((size_t)e * FDIM + f0) * CDIM;
    const float* b2base = g_w3t + ((size_t)e * FDIM + f0) * CDIM;

#if USE_TC
    extern __shared__ char dynsmem[];
    uint32_t raw = smem_u32(dynsmem);
    uint32_t sbase = (raw + 1023) & ~1023u;
    char* smb = dynsmem + (sbase - raw);
    uint32_t ctrl = sbase + G1_CTRL;
    int*   s_tok = (int*)(smb + G1_CTRL + 64);
    float* s_w   = (float*)(smb + G1_CTRL + 576);

    int wid = t >> 5, lid = t & 31;
    if (wid == 0) { TC_ALLOC(ctrl, 256); TC_RELINQ(); }
    if (t < 128) {
        int tk = g_tok[r0 + t];
        s_tok[t] = tk < 0 ? 0 : tk;
        s_w[t]   = tk < 0 ? 0.f : g_w[r0 + t];
    }
    if (t == 0) {
        MBAR_INIT(ctrl + 16, 224); MBAR_INIT(ctrl + 24, 224);
        MBAR_INIT(ctrl + 32, 1);   MBAR_INIT(ctrl + 40, 1);
        MBAR_INIT(ctrl + 48, 1);
    }
    __syncthreads();
    uint32_t tmem;
    asm volatile("ld.shared.b32 %0, [%1];" : "=r"(tmem) : "r"(ctrl));

    const int NC = CDIM / 32;   // 64 chunks
    if (wid != 0) {
        // ---------------- producers: warps 1-7 (224 threads) ----------------
        int tp = t - 32;
        int phd0 = 0, phd1 = 0;
        for (int kc = 0; kc < NC; kc++) {
            int s = kc & 1;
            if (kc >= 2) {
                if (s == 0) { mbar_wait(ctrl + 32, phd0); phd0 ^= 1; }
                else        { mbar_wait(ctrl + 40, phd1); phd1 ^= 1; }
            }
            int k0 = kc * 32;
            for (int idx = tp; idx < 3072; idx += 224) {
                int sub = idx & 1023;
                int row = sub >> 3, c4 = sub & 7;
                uint32_t soff = SWZ(row * 128 + c4 * 16);
                if (idx < 1024) {
                    CP_ASYNC16(sbase + G1_A(s) + soff,
                               g_xt + (size_t)s_tok[row] * CDIM + k0 + c4 * 4);
                } else if (idx < 2048) {
                    CP_ASYNC16(sbase + G1_B1(s) + soff,
                               b1base + (size_t)row * CDIM + k0 + c4 * 4);
                } else {
                    CP_ASYNC16(sbase + G1_B2(s) + soff,
                               b2base + (size_t)row * CDIM + k0 + c4 * 4);
                }
            }
            CP_MBAR_ARRIVE(ctrl + 16 + s * 8);
        }
    } else {
        // ---------------- consumer: warp 0 (MMA only) ----------------
        int phf0 = 0, phf1 = 0;
        for (int kc = 0; kc < NC; kc++) {
            int s = kc & 1;
            if (s == 0) { mbar_wait(ctrl + 16, phf0); phf0 ^= 1; }
            else        { mbar_wait(ctrl + 24, phf1); phf1 ^= 1; }
            if (elect_one()) {
                FENCE_ASYNC();
                uint64_t ad  = make_desc(sbase + G1_A(s));
                uint64_t b1d = make_desc(sbase + G1_B1(s));
                uint64_t b2d = make_desc(sbase + G1_B2(s));
                #pragma unroll
                for (int j = 0; j < 4; j++) {
                    uint32_t acc = (kc > 0 || j > 0) ? 1u : 0u;
                    mma_tf32_ss(tmem + 0,   ad + j*2, b1d + j*2, IDESC_N128, acc);
                    mma_tf32_ss(tmem + 128, ad + j*2, b2d + j*2, IDESC_N128, acc);
                }
                if (kc == NC - 1) TC_COMMIT(ctrl + 48);     // fin
                else              TC_COMMIT(ctrl + 32 + s * 8);
            }
        }
    }
    // all warps: wait for final MMA completion
    mbar_wait(ctrl + 48, 0);
    TC_FENCE_AFTER();

    {   // 8-warp epilogue: warp = (subpartition wid&3) x (column half wid>>2, 64 cols)
        int wq = wid & 3, half = wid >> 2;
        int m = wq * 32 + lid;
        float wgt = s_w[m];
        float* hrow = g_H + (size_t)(r0 + m) * FDIM + f0 + half * 64;
        #pragma unroll
        for (int base = 0; base < 64; base += 32) {
            uint32_t rg[32], ru[32];
            TMEM_LD32(rg, tmem + half * 64 + base);
            TMEM_LD32(ru, tmem + 128 + half * 64 + base);
            TC_WAIT_LD();
            #pragma unroll
            for (int j = 0; j < 32; j += 4) {
                float4 h4;
                float hv[4];
                #pragma unroll
                for (int q = 0; q < 4; q++) {
                    float g = __uint_as_float(rg[j+q]);
                    float u = __uint_as_float(ru[j+q]);
                    float sig = 0.5f * fast_tanh(0.5f * g) + 0.5f;
                    hv[q] = to_tf32(g * sig * u * wgt);
                }
                h4.x = hv[0]; h4.y = hv[1]; h4.z = hv[2]; h4.w = hv[3];
                *(float4*)(hrow + base + j) = h4;
            }
        }
        TC_FENCE_BEFORE();
    }
    __syncthreads();
    if (wid == 0) TC_DEALLOC(tmem, 256);
#else
    // FFMA fallback (compute_103 PTX insurance)
    int row = t & 127, half = t >> 7;
    int tk = g_tok[r0 + row];
    float wgt = tk < 0 ? 0.f : g_w[r0 + row];
    int mytok = tk < 0 ? 0 : tk;
    const float* xr = g_xt + (size_t)mytok * CDIM;
    for (int c = 0; c < 64; c++) {
        int col = half * 64 + c;
        const float* w1r = b1base + (size_t)col * CDIM;
        const float* w3r = b2base + (size_t)col * CDIM;
        float sg = 0.f, su = 0.f;
        for (int k = 0; k < CDIM; k += 4) {
            float4 xv = *(const float4*)(xr + k);
            float4 a = *(const float4*)(w1r + k);
            float4 b = *(const float4*)(w3r + k);
            sg += xv.x*a.x + xv.y*a.y + xv.z*a.z + xv.w*a.w;
            su += xv.x*b.x + xv.y*b.y + xv.z*b.z + xv.w*b.w;
        }
        g_H[(size_t)(r0 + row) * FDIM + f0 + col] = sg / (1.f + __expf(-sg)) * su * wgt;
    }
#endif
}

// ======== GEMM2: warp-specialized, M=128 N=256/CTA, 2 CTAs/SM -> permuted g_O ========
#define G2_A(s)  ((s)*16384)
#define G2_B(s)  (32768 + (s)*32768)
#define G2_CTRL  98304
#define G2_SMEM  (98304 + 64 + 1024)

__global__ __launch_bounds__(256, 2) void gemm2_kernel() {
    int e = blockIdx.z;
    int cnt = g_cnt[e];
    int rt = blockIdx.x;
    if (rt * 128 >= cnt) return;
    int r0 = g_base[e] + rt * 128;
    int c0 = blockIdx.y * 256;
    int t = threadIdx.x;
    const float* Bbase = g_w2t + ((size_t)e * CDIM + c0) * FDIM;

#if USE_TC
    extern __shared__ char dynsmem[];
    uint32_t raw = smem_u32(dynsmem);
    uint32_t sbase = (raw + 1023) & ~1023u;
    char* smb = dynsmem + (sbase - raw);
    (void)smb;
    uint32_t ctrl = sbase + G2_CTRL;

    int wid = t >> 5, lid = t & 31;
    if (wid == 0) { TC_ALLOC(ctrl, 256); TC_RELINQ(); }
    if (t == 0) {
        MBAR_INIT(ctrl + 16, 224); MBAR_INIT(ctrl + 24, 224);
        MBAR_INIT(ctrl + 32, 1);   MBAR_INIT(ctrl + 40, 1);
        MBAR_INIT(ctrl + 48, 1);
    }
    __syncthreads();
    uint32_t tmem;
    asm volatile("ld.shared.b32 %0, [%1];" : "=r"(tmem) : "r"(ctrl));

    const float* Abase = g_H + (size_t)r0 * FDIM;
    const int NC = FDIM / 32;   // 32 chunks

    if (wid != 0) {
        int tp = t - 32;
        int phd0 = 0, phd1 = 0;
        for (int kc = 0; kc < NC; kc++) {
            int s = kc & 1;
            if (kc >= 2) {
                if (s == 0) { mbar_wait(ctrl + 32, phd0); phd0 ^= 1; }
                else        { mbar_wait(ctrl + 40, phd1); phd1 ^= 1; }
            }
            int k0 = kc * 32;
            for (int idx = tp; idx < 3072; idx += 224) {
                if (idx < 1024) {
                    int row = idx >> 3, c4 = idx & 7;
                    CP_ASYNC16(sbase + G2_A(s) + SWZ(row * 128 + c4 * 16),
                               Abase + (size_t)row * FDIM + k0 + c4 * 4);
                } else {
                    int sub = idx - 1024;
                    int row = sub >> 3, c4 = sub & 7;   // 0..255
                    CP_ASYNC16(sbase + G2_B(s) + SWZ(row * 128 + c4 * 16),
                               Bbase + (size_t)row * FDIM + k0 + c4 * 4);
                }
            }
            CP_MBAR_ARRIVE(ctrl + 16 + s * 8);
        }
    } else {
        int phf0 = 0, phf1 = 0;
        for (int kc = 0; kc < NC; kc++) {
            int s = kc & 1;
            if (s == 0) { mbar_wait(ctrl + 16, phf0); phf0 ^= 1; }
            else        { mbar_wait(ctrl + 24, phf1); phf1 ^= 1; }
            if (elect_one()) {
                FENCE_ASYNC();
                uint64_t ad = make_desc(sbase + G2_A(s));
                uint64_t bd = make_desc(sbase + G2_B(s));
                #pragma unroll
                for (int j = 0; j < 4; j++) {
                    uint32_t acc = (kc > 0 || j > 0) ? 1u : 0u;
                    mma_tf32_ss(tmem, ad + j*2, bd + j*2, IDESC_N256, acc);
                }
                if (kc == NC - 1) TC_COMMIT(ctrl + 48);
                else              TC_COMMIT(ctrl + 32 + s * 8);
            }
        }
    }
    mbar_wait(ctrl + 48, 0);
    TC_FENCE_AFTER();

    {   // epilogue: 8 warps = (subpartition wid&3) x (column half wid>>2, 128 cols)
        int wq = wid & 3, half = wid >> 2;
        int m = wq * 32 + lid;
        float* orow = g_O + (size_t)(r0 + m) * CDIM + c0 + half * 128;
        #pragma unroll
        for (int base = 0; base < 128; base += 32) {
            uint32_t r[32];
            TMEM_LD32(r, tmem + half * 128 + base);
            TC_WAIT_LD();
            #pragma unroll
            for (int j = 0; j < 32; j += 4) {
                float4 v;
                v.x = __uint_as_float(r[j+0]);
                v.y = __uint_as_float(r[j+1]);
                v.z = __uint_as_float(r[j+2]);
                v.w = __uint_as_float(r[j+3]);
                *(float4*)(orow + base + j) = v;
            }
        }
        TC_FENCE_BEFORE();
    }
    __syncthreads();
    if (wid == 0) TC_DEALLOC(tmem, 256);
#else
    // FFMA fallback
    int row = t & 127, half = t >> 7;
    const float* hr = g_H + (size_t)(r0 + row) * FDIM;
    for (int c = 0; c < 128; c++) {
        int col = half * 128 + c;
        const float* w2r = Bbase + (size_t)col * FDIM;
        float sv = 0.f;
        for (int k = 0; k < FDIM; k += 4) {
            float4 hv = *(const float4*)(hr + k);
            float4 b = *(const float4*)(w2r + k);
            sv += hv.x*b.x + hv.y*b.y + hv.z*b.z + hv.w*b.w;
        }
        g_O[(size_t)(r0 + row) * CDIM + c0 + col] = sv;
    }
#endif
}

// ---------------- combine: out[t] = O[p0] + O[p1] ----------------
__global__ void combine_kernel(float4* __restrict__ out4) {
    int v = blockIdx.x * blockDim.x + threadIdx.x;
    int tk = v >> 9, c4 = v & 511;
    int p0 = g_pos[tk*2], p1 = g_pos[tk*2+1];
    const float4* O4 = (const float4*)g_O;
    float4 a = O4[(size_t)p0 * 512 + c4];
    float4 b = O4[(size_t)p1 * 512 + c4];
    out4[v] = make_float4(a.x + b.x, a.y + b.y, a.z + b.z, a.w + b.w);
}

// ---------------- launch ----------------
extern "C" void kernel_launch(void* const* d_in, const int* in_sizes, int n_in,
                              void* d_out, int out_size) {
    const float* x  = (const float*)d_in[0];
    const float* wr = (const float*)d_in[1];
    const float* w1 = (const float*)d_in[2];
    const float* w3 = (const float*)d_in[3];
    const float* w2 = (const float*)d_in[4];
    float* out = (float*)d_out;

    cudaFuncSetAttribute(gemm1_kernel, cudaFuncAttributeMaxDynamicSharedMemorySize, G1_SMEM);
    cudaFuncSetAttribute(gemm2_kernel, cudaFuncAttributeMaxDynamicSharedMemorySize, G2_SMEM);

    // profiled launch is index 3 (0-based) -> gemm1
    prep_kernel<<<dim3(8192, 4), 256>>>((const float4*)x, w1, w3, w2);   // 0
    router_kernel<<<NTOK, 256>>>(x, wr);                                  // 1
    offsets_scatter_kernel<<<1, 1024>>>();                                // 2
    gemm1_kernel<<<dim3(64, FDIM/128, NEXP), 256, G1_SMEM>>>();           // 3 <- profiled
    gemm2_kernel<<<dim3(64, CDIM/256, NEXP), 256, G2_SMEM>>>();           // 4
    combine_kernel<<<(NTOK * (CDIM/4)) / 256, 256>>>((float4*)out);       // 5
}

// round 15
// speedup vs baseline: 1.1204x; 1.1204x over previous
#include <cuda_runtime.h>
#include <math.h>
#include <stdint.h>

#if defined(__CUDA_ARCH__) && defined(__CUDA_ARCH_FEAT_SM103_ALL)
#define USE_TC 1
#else
#define USE_TC 0
#endif

#define NTOK 4096
#define CDIM 2048
#define FDIM 1024
#define NEXP 8
#define RPAD (2*NTOK + NEXP*128)   // 8704 padded permuted rows

// ---------------- device scratch ----------------
__device__ int   g_te[NTOK*2];
__device__ float g_tp[NTOK*2];
__device__ int   g_cnt[NEXP];
__device__ int   g_base[NEXP];
__device__ int   g_tok[RPAD];
__device__ float g_w[RPAD];
__device__ int   g_pos[NTOK*2];
__device__ float g_xt[(size_t)NTOK * CDIM];        // tf32-rounded x
__device__ float g_H[(size_t)RPAD * FDIM];
__device__ float g_O[(size_t)RPAD * CDIM];
__device__ float g_w1t[(size_t)NEXP*FDIM*CDIM];    // [E][F][C] K-major tf32
__device__ float g_w3t[(size_t)NEXP*FDIM*CDIM];
__device__ float g_w2t[(size_t)NEXP*CDIM*FDIM];    // [E][C][F] K-major tf32

// ---------------- helpers ----------------
__device__ __forceinline__ uint32_t smem_u32(const void* p) {
    uint32_t a;
    asm("{ .reg .u64 t; cvta.to.shared.u64 t, %1; cvt.u32.u64 %0, t; }" : "=r"(a) : "l"(p));
    return a;
}
__device__ __forceinline__ float to_tf32(float x) {
    float r; asm("cvt.rna.tf32.f32 %0, %1;" : "=f"(r) : "f"(x)); return r;
}

#if USE_TC
__device__ __forceinline__ uint32_t elect_one() {
    uint32_t p;
    asm volatile("{ .reg .pred p; elect.sync _|p, 0xFFFFFFFF; selp.b32 %0, 1, 0, p; }" : "=r"(p));
    return p;
}
__device__ __forceinline__ float fast_tanh(float x) {
    float r; asm("tanh.approx.f32 %0, %1;" : "=f"(r) : "f"(x)); return r;
}
#define MBAR_INIT(a, c) asm volatile("mbarrier.init.shared.b64 [%0], %1;" :: "r"(a), "r"(c) : "memory")
__device__ __forceinline__ void mbar_wait(uint32_t addr, uint32_t parity) {
    asm volatile(
        "{\n\t.reg .pred P;\n\t"
        "W_%=:\n\t"
        "mbarrier.try_wait.parity.acquire.cta.shared::cta.b64 P, [%0], %1, 0x989680;\n\t"
        "@P bra D_%=;\n\t"
        "bra W_%=;\n\t"
        "D_%=:\n\t}"
        :: "r"(addr), "r"(parity) : "memory");
}
#define TC_ALLOC(sa, n)   asm volatile("tcgen05.alloc.cta_group::1.sync.aligned.shared::cta.b32 [%0], %1;" :: "r"(sa), "r"(n) : "memory")
#define TC_DEALLOC(t, n)  asm volatile("tcgen05.dealloc.cta_group::1.sync.aligned.b32 %0, %1;" :: "r"(t), "r"(n))
#define TC_RELINQ()       asm volatile("tcgen05.relinquish_alloc_permit.cta_group::1.sync.aligned;")
#define TC_COMMIT(mb)     asm volatile("tcgen05.commit.cta_group::1.mbarrier::arrive::one.shared::cluster.b64 [%0];" :: "r"(mb) : "memory")
#define TC_FENCE_AFTER()  asm volatile("tcgen05.fence::after_thread_sync;" ::: "memory")
#define TC_FENCE_BEFORE() asm volatile("tcgen05.fence::before_thread_sync;" ::: "memory")
#define TC_WAIT_LD()      asm volatile("tcgen05.wait::ld.sync.aligned;" ::: "memory")
#define FENCE_ASYNC()     asm volatile("fence.proxy.async.shared::cta;" ::: "memory")

#define CP_ASYNC16(sm, gm) asm volatile("cp.async.cg.shared.global [%0], [%1], 16;" :: "r"(sm), "l"(gm) : "memory")
#define CP_COMMIT()        asm volatile("cp.async.commit_group;" ::: "memory")
#define CP_WAIT1()         asm volatile("cp.async.wait_group 1;" ::: "memory")
#define CP_WAIT0()         asm volatile("cp.async.wait_group 0;" ::: "memory")

__device__ __forceinline__ void mma_tf32_ss(uint32_t d, uint64_t a, uint64_t b,
                                            uint32_t idesc, uint32_t acc) {
    asm volatile(
        "{\n\t.reg .pred p;\n\tsetp.ne.u32 p, %5, 0;\n\t"
        "tcgen05.mma.cta_group::1.kind::tf32 [%0], %1, %2, %3, {%4, %4, %4, %4}, p;\n\t}"
        :: "r"(d), "l"(a), "l"(b), "r"(idesc), "r"(0u), "r"(acc) : "memory");
}

#define TMEM_LD32(r, a) \
    asm volatile("tcgen05.ld.sync.aligned.32x32b.x32.b32 " \
        "{%0,%1,%2,%3,%4,%5,%6,%7,%8,%9,%10,%11,%12,%13,%14,%15," \
        "%16,%17,%18,%19,%20,%21,%22,%23,%24,%25,%26,%27,%28,%29,%30,%31}, [%32];" \
        : "=r"((r)[0]),"=r"((r)[1]),"=r"((r)[2]),"=r"((r)[3]),"=r"((r)[4]),"=r"((r)[5]),"=r"((r)[6]),"=r"((r)[7]), \
          "=r"((r)[8]),"=r"((r)[9]),"=r"((r)[10]),"=r"((r)[11]),"=r"((r)[12]),"=r"((r)[13]),"=r"((r)[14]),"=r"((r)[15]), \
          "=r"((r)[16]),"=r"((r)[17]),"=r"((r)[18]),"=r"((r)[19]),"=r"((r)[20]),"=r"((r)[21]),"=r"((r)[22]),"=r"((r)[23]), \
          "=r"((r)[24]),"=r"((r)[25]),"=r"((r)[26]),"=r"((r)[27]),"=r"((r)[28]),"=r"((r)[29]),"=r"((r)[30]),"=r"((r)[31]) \
        : "r"(a))

static __device__ __forceinline__ uint64_t make_desc(uint32_t addr) {
    const uint64_t base =
        (uint64_t(2) << 61) | (uint64_t(1) << 46) | (uint64_t(64) << 32) | (uint64_t(1) << 16);
    return base | ((uint64_t)(addr >> 4) & 0x3FFF);
}
#define SWZ(o) ((o) ^ (((o) >> 3) & 0x70))
#define IDESC_N256 (0x10u | (2u<<7) | (2u<<10) | ((256u/8u)<<17) | ((128u/16u)<<24))
#endif // USE_TC

// ---------------- prep: transposes (y=0..2) + xt/init (y=3) ----------------
__global__ __launch_bounds__(256) void prep_kernel(
    const float4* __restrict__ x4,
    const float* __restrict__ w1, const float* __restrict__ w3,
    const float* __restrict__ w2) {
    int which = blockIdx.y;
    if (which == 3) {
        int i = blockIdx.x * blockDim.x + threadIdx.x;
        float4 v = x4[i];
        v.x = to_tf32(v.x); v.y = to_tf32(v.y); v.z = to_tf32(v.z); v.w = to_tf32(v.w);
        ((float4*)g_xt)[i] = v;
        if (i < RPAD) g_tok[i] = -1;
        if (i < NEXP) g_cnt[i] = 0;
        return;
    }
    if (blockIdx.x >= 4096) return;
    __shared__ float ts[32][129];
    const float* in;
    float* out;
    int R, Cc;
    if (which == 0)      { in = w1; out = g_w1t; R = CDIM; Cc = FDIM; }
    else if (which == 1) { in = w3; out = g_w3t; R = CDIM; Cc = FDIM; }
    else                 { in = w2; out = g_w2t; R = FDIM; Cc = CDIM; }
    int nx = Cc / 128;
    int e = blockIdx.x / (nx * (R / 32));
    int rem = blockIdx.x % (nx * (R / 32));
    int cx = rem % nx, rx = rem / nx;
    size_t eoff = (size_t)e * R * Cc;
    int c0 = cx * 128;
    int r0 = rx * 32;
    int tx = threadIdx.x & 31, ty = threadIdx.x >> 5;
    #pragma unroll
    for (int j = ty; j < 32; j += 8) {
        float4 v = *(const float4*)(in + eoff + (size_t)(r0 + j) * Cc + c0 + tx * 4);
        ts[j][tx*4+0] = to_tf32(v.x);
        ts[j][tx*4+1] = to_tf32(v.y);
        ts[j][tx*4+2] = to_tf32(v.z);
        ts[j][tx*4+3] = to_tf32(v.w);
    }
    __syncthreads();
    int t = threadIdx.x;
    #pragma unroll
    for (int i = 0; i < 4; i++) {
        int idx = t + i * 256;
        int oc = idx >> 3;
        int q4 = idx & 7;
        float4 v;
        v.x = ts[q4*4+0][oc];
        v.y = ts[q4*4+1][oc];
        v.z = ts[q4*4+2][oc];
        v.w = ts[q4*4+3][oc];
        *(float4*)(out + eoff + (size_t)(c0 + oc) * R + r0 + q4 * 4) = v;
    }
}

// ---------------- router ----------------
__global__ void router_kernel(const float* __restrict__ x, const float* __restrict__ wr) {
    __shared__ float xs[CDIM];
    __shared__ float lg[NEXP];
    int t = blockIdx.x;
    const float4* xrow = (const float4*)(x + (size_t)t * CDIM);
    for (int i = threadIdx.x; i < CDIM / 4; i += blockDim.x)
        ((float4*)xs)[i] = xrow[i];
    __syncthreads();
    int warp = threadIdx.x >> 5, lane = threadIdx.x & 31;
    float s = 0.f;
    #pragma unroll 8
    for (int c = lane; c < CDIM; c += 32) s += xs[c] * wr[c * NEXP + warp];
    #pragma unroll
    for (int o = 16; o > 0; o >>= 1) s += __shfl_xor_sync(0xFFFFFFFFu, s, o);
    if (lane == 0) lg[warp] = s;
    __syncthreads();
    if (threadIdx.x == 0) {
        int i0 = 0; float v0 = lg[0];
        #pragma unroll
        for (int e = 1; e < NEXP; e++) if (lg[e] > v0) { v0 = lg[e]; i0 = e; }
        int i1 = -1; float v1 = -INFINITY;
        #pragma unroll
        for (int e = 0; e < NEXP; e++) if (e != i0 && lg[e] > v1) { v1 = lg[e]; i1 = e; }
        float e1 = __expf(v1 - v0);
        float inv = 1.f / (1.f + e1);
        g_te[t*2+0] = i0; g_tp[t*2+0] = inv;
        g_te[t*2+1] = i1; g_tp[t*2+1] = e1 * inv;
        atomicAdd(&g_cnt[i0], 1);
        atomicAdd(&g_cnt[i1], 1);
    }
}

// ---------------- offsets + scatter fused (single block) ----------------
__global__ __launch_bounds__(1024) void offsets_scatter_kernel() {
    __shared__ int s_fill[NEXP];
    if (threadIdx.x == 0) {
        int b = 0;
        #pragma unroll
        for (int e = 0; e < NEXP; e++) {
            g_base[e] = b;
            b += ((g_cnt[e] + 127) >> 7) << 7;
        }
    }
    if (threadIdx.x < NEXP) s_fill[threadIdx.x] = 0;
    __syncthreads();
    for (int t = threadIdx.x; t < NTOK; t += 1024) {
        #pragma unroll
        for (int k = 0; k < 2; k++) {
            int e = g_te[t*2+k];
            int pos = g_base[e] + atomicAdd(&s_fill[e], 1);
            g_tok[pos] = t;
            g_w[pos] = g_tp[t*2+k];
            g_pos[t*2+k] = pos;
        }
    }
}

// ---- GEMM1: M=128, one N=256 MMA over contiguous [B1|B2], 2 CTAs/SM, SwiGLU ----
#define G1_A(s)  ((s)*16384)
#define G1_B(s)  (32768 + (s)*32768)   // [B1 16K | B2 16K] contiguous
#define G1_CTRL  98304
#define G1_SMEM  (98304 + 64 + 1024 + 1024)

__global__ __launch_bounds__(256, 2) void gemm1_kernel() {
    int e = blockIdx.z;
    int cnt = g_cnt[e];
    int rt = blockIdx.x;
    if (rt * 128 >= cnt) return;
    int r0 = g_base[e] + rt * 128;
    int f0 = blockIdx.y * 128;
    int t = threadIdx.x;
    const float* b1base = g_w1t + ((size_t)e * FDIM + f0) * CDIM;
    const float* b2base = g_w3t + ((size_t)e * FDIM + f0) * CDIM;

#if USE_TC
    extern __shared__ char dynsmem[];
    uint32_t raw = smem_u32(dynsmem);
    uint32_t sbase = (raw + 1023) & ~1023u;
    char* smb = dynsmem + (sbase - raw);
    uint32_t ctrl = sbase + G1_CTRL;
    int*   s_tok = (int*)(smb + G1_CTRL + 64);
    float* s_w   = (float*)(smb + G1_CTRL + 576);

    int wid = t >> 5, lid = t & 31;
    if (wid == 0) { TC_ALLOC(ctrl, 256); TC_RELINQ(); }
    if (t < 128) {
        int tk = g_tok[r0 + t];
        s_tok[t] = tk < 0 ? 0 : tk;
        s_w[t]   = tk < 0 ? 0.f : g_w[r0 + t];
    }
    if (t == 0) { MBAR_INIT(ctrl + 16, 1); MBAR_INIT(ctrl + 24, 1); }
    __syncthreads();
    uint32_t tmem;
    asm volatile("ld.shared.b32 %0, [%1];" : "=r"(tmem) : "r"(ctrl));

    auto load_chunk = [&](int kc, int s) {
        int k0 = kc * 32;
        #pragma unroll
        for (int i = 0; i < 4; i++) {          // A: 128 rows x 32
            int idx = t + i * 256;
            int row = idx >> 3, c4 = idx & 7;
            const float* src = g_xt + (size_t)s_tok[row] * CDIM + k0 + c4 * 4;
            CP_ASYNC16(sbase + G1_A(s) + SWZ(row * 128 + c4 * 16), src);
        }
        // B: 256 rows contiguous (rows 0..127 = w1, 128..255 = w3); SWZ depends
        // only on row&7 so one expression covers the whole 32 KB region.
        #pragma unroll
        for (int i = 0; i < 8; i++) {
            int idx = t + i * 256;             // 0..2047
            int row = idx >> 3, c4 = idx & 7;  // row 0..255
            const float* src = (i < 4)
                ? b1base + (size_t)row * CDIM + k0 + c4 * 4
                : b2base + (size_t)(row - 128) * CDIM + k0 + c4 * 4;
            CP_ASYNC16(sbase + G1_B(s) + SWZ(row * 128 + c4 * 16), src);
        }
        CP_COMMIT();
    };

    load_chunk(0, 0);
    int ph0 = 0, ph1 = 0;
    for (int kc = 0; kc < CDIM / 32; kc++) {
        int s = kc & 1;
        if (kc + 1 < CDIM / 32) {
            if (kc >= 1) {
                if ((s ^ 1) == 0) { mbar_wait(ctrl + 16, ph0); ph0 ^= 1; }
                else              { mbar_wait(ctrl + 24, ph1); ph1 ^= 1; }
            }
            load_chunk(kc + 1, s ^ 1);
            CP_WAIT1();
        } else {
            CP_WAIT0();
        }
        __syncthreads();
        if (wid == 0 && elect_one()) {
            FENCE_ASYNC();
            uint64_t ad = make_desc(sbase + G1_A(s));
            uint64_t bd = make_desc(sbase + G1_B(s));
            #pragma unroll
            for (int j = 0; j < 4; j++) {
                uint32_t acc = (kc > 0 || j > 0) ? 1u : 0u;
                mma_tf32_ss(tmem, ad + j*2, bd + j*2, IDESC_N256, acc);
            }
            TC_COMMIT(ctrl + 16 + s * 8);
        }
    }
    mbar_wait(ctrl + 24, ph1);
    TC_FENCE_AFTER();

    {   // 8-warp epilogue: D cols 0-127 = g, 128-255 = u
        int wq = wid & 3, half = wid >> 2;
        int m = wq * 32 + lid;
        float wgt = s_w[m];
        float* hrow = g_H + (size_t)(r0 + m) * FDIM + f0 + half * 64;
        #pragma unroll
        for (int base = 0; base < 64; base += 32) {
            uint32_t rg[32], ru[32];
            TMEM_LD32(rg, tmem + half * 64 + base);
            TMEM_LD32(ru, tmem + 128 + half * 64 + base);
            TC_WAIT_LD();
            #pragma unroll
            for (int j = 0; j < 32; j += 4) {
                float4 h4;
                float hv[4];
                #pragma unroll
                for (int q = 0; q < 4; q++) {
                    float g = __uint_as_float(rg[j+q]);
                    float u = __uint_as_float(ru[j+q]);
                    float sig = 0.5f * fast_tanh(0.5f * g) + 0.5f;
                    hv[q] = to_tf32(g * sig * u * wgt);
                }
                h4.x = hv[0]; h4.y = hv[1]; h4.z = hv[2]; h4.w = hv[3];
                *(float4*)(hrow + base + j) = h4;
            }
        }
        TC_FENCE_BEFORE();
    }
    __syncthreads();
    if (wid == 0) TC_DEALLOC(tmem, 256);
#else
    // FFMA fallback (compute_103 PTX insurance)
    int row = t & 127, half = t >> 7;
    int tk = g_tok[r0 + row];
    float wgt = tk < 0 ? 0.f : g_w[r0 + row];
    int mytok = tk < 0 ? 0 : tk;
    const float* xr = g_xt + (size_t)mytok * CDIM;
    for (int c = 0; c < 64; c++) {
        int col = half * 64 + c;
        const float* w1r = b1base + (size_t)col * CDIM;
        const float* w3r = b2base + (size_t)col * CDIM;
        float sg = 0.f, su = 0.f;
        for (int k = 0; k < CDIM; k += 4) {
            float4 xv = *(const float4*)(xr + k);
            float4 a = *(const float4*)(w1r + k);
            float4 b = *(const float4*)(w3r + k);
            sg += xv.x*a.x + xv.y*a.y + xv.z*a.z + xv.w*a.w;
            su += xv.x*b.x + xv.y*b.y + xv.z*b.z + xv.w*b.w;
        }
        g_H[(size_t)(r0 + row) * FDIM + f0 + col] = sg / (1.f + __expf(-sg)) * su * wgt;
    }
#endif
}

// ---------------- GEMM2: M=128 N=256/CTA, 2 CTAs/SM -> permuted g_O ----------------
#define G2_A(s)  ((s)*16384)
#define G2_B(s)  (32768 + (s)*32768)
#define G2_CTRL  98304
#define G2_SMEM  (98304 + 64 + 1024)

__global__ __launch_bounds__(256, 2) void gemm2_kernel() {
    int e = blockIdx.z;
    int cnt = g_cnt[e];
    int rt = blockIdx.x;
    if (rt * 128 >= cnt) return;
    int r0 = g_base[e] + rt * 128;
    int c0 = blockIdx.y * 256;
    int t = threadIdx.x;
    const float* Bbase = g_w2t + ((size_t)e * CDIM + c0) * FDIM;

#if USE_TC
    extern __shared__ char dynsmem[];
    uint32_t raw = smem_u32(dynsmem);
    uint32_t sbase = (raw + 1023) & ~1023u;
    char* smb = dynsmem + (sbase - raw);
    (void)smb;
    uint32_t ctrl = sbase + G2_CTRL;

    int wid = t >> 5, lid = t & 31;
    if (wid == 0) { TC_ALLOC(ctrl, 256); TC_RELINQ(); }
    if (t == 0) { MBAR_INIT(ctrl + 16, 1); MBAR_INIT(ctrl + 24, 1); }
    __syncthreads();
    uint32_t tmem;
    asm volatile("ld.shared.b32 %0, [%1];" : "=r"(tmem) : "r"(ctrl));

    const float* Abase = g_H + (size_t)r0 * FDIM;

    auto load_chunk = [&](int kc, int s) {
        int k0 = kc * 32;
        #pragma unroll
        for (int i = 0; i < 4; i++) {
            int idx = t + i * 256;
            int row = idx >> 3, c4 = idx & 7;
            CP_ASYNC16(sbase + G2_A(s) + SWZ(row * 128 + c4 * 16),
                       Abase + (size_t)row * FDIM + k0 + c4 * 4);
        }
        #pragma unroll
        for (int i = 0; i < 8; i++) {
            int idx = t + i * 256;
            int row = idx >> 3, c4 = idx & 7;
            CP_ASYNC16(sbase + G2_B(s) + SWZ(row * 128 + c4 * 16),
                       Bbase + (size_t)row * FDIM + k0 + c4 * 4);
        }
        CP_COMMIT();
    };

    load_chunk(0, 0);
    int ph0 = 0, ph1 = 0;
    for (int kc = 0; kc < FDIM / 32; kc++) {
        int s = kc & 1;
        if (kc + 1 < FDIM / 32) {
            if (kc >= 1) {
                if ((s ^ 1) == 0) { mbar_wait(ctrl + 16, ph0); ph0 ^= 1; }
                else              { mbar_wait(ctrl + 24, ph1); ph1 ^= 1; }
            }
            load_chunk(kc + 1, s ^ 1);
            CP_WAIT1();
        } else {
            CP_WAIT0();
        }
        __syncthreads();
        if (wid == 0 && elect_one()) {
            FENCE_ASYNC();
            uint64_t ad = make_desc(sbase + G2_A(s));
            uint64_t bd = make_desc(sbase + G2_B(s));
            #pragma unroll
            for (int j = 0; j < 4; j++) {
                uint32_t acc = (kc > 0 || j > 0) ? 1u : 0u;
                mma_tf32_ss(tmem, ad + j*2, bd + j*2, IDESC_N256, acc);
            }
            TC_COMMIT(ctrl + 16 + s * 8);
        }
    }
    mbar_wait(ctrl + 24, ph1);
    TC_FENCE_AFTER();

    {   // epilogue: 8 warps = (subpartition wid&3) x (column half wid>>2, 128 cols)
        int wq = wid & 3, half = wid >> 2;
        int m = wq * 32 + lid;
        float* orow = g_O + (size_t)(r0 + m) * CDIM + c0 + half * 128;
        #pragma unroll
        for (int base = 0; base < 128; base += 32) {
            uint32_t r[32];
            TMEM_LD32(r, tmem + half * 128 + base);
            TC_WAIT_LD();
            #pragma unroll
            for (int j = 0; j < 32; j += 4) {
                float4 v;
                v.x = __uint_as_float(r[j+0]);
                v.y = __uint_as_float(r[j+1]);
                v.z = __uint_as_float(r[j+2]);
                v.w = __uint_as_float(r[j+3]);
                *(float4*)(orow + base + j) = v;
            }
        }
        TC_FENCE_BEFORE();
    }
    __syncthreads();
    if (wid == 0) TC_DEALLOC(tmem, 256);
#else
    // FFMA fallback
    int row = t & 127, half = t >> 7;
    const float* hr = g_H + (size_t)(r0 + row) * FDIM;
    for (int c = 0; c < 128; c++) {
        int col = half * 128 + c;
        const float* w2r = Bbase + (size_t)col * FDIM;
        float sv = 0.f;
        for (int k = 0; k < FDIM; k += 4) {
            float4 hv = *(const float4*)(hr + k);
            float4 b = *(const float4*)(w2r + k);
            sv += hv.x*b.x + hv.y*b.y + hv.z*b.z + hv.w*b.w;
        }
        g_O[(size_t)(r0 + row) * CDIM + c0 + col] = sv;
    }
#endif
}

// ---------------- combine: out[t] = O[p0] + O[p1] ----------------
__global__ void combine_kernel(float4* __restrict__ out4) {
    int v = blockIdx.x * blockDim.x + threadIdx.x;
    int tk = v >> 9, c4 = v & 511;
    int p0 = g_pos[tk*2], p1 = g_pos[tk*2+1];
    const float4* O4 = (const float4*)g_O;
    float4 a = O4[(size_t)p0 * 512 + c4];
    float4 b = O4[(size_t)p1 * 512 + c4];
    out4[v] = make_float4(a.x + b.x, a.y + b.y, a.z + b.z, a.w + b.w);
}

// ---------------- launch ----------------
extern "C" void kernel_launch(void* const* d_in, const int* in_sizes, int n_in,
                              void* d_out, int out_size) {
    const float* x  = (const float*)d_in[0];
    const float* wr = (const float*)d_in[1];
    const float* w1 = (const float*)d_in[2];
    const float* w3 = (const float*)d_in[3];
    const float* w2 = (const float*)d_in[4];
    float* out = (float*)d_out;

    cudaFuncSetAttribute(gemm1_kernel, cudaFuncAttributeMaxDynamicSharedMemorySize, G1_SMEM);
    cudaFuncSetAttribute(gemm2_kernel, cudaFuncAttributeMaxDynamicSharedMemorySize, G2_SMEM);

    // profiled launch is index 3 (0-based) -> gemm1
    prep_kernel<<<dim3(8192, 4), 256>>>((const float4*)x, w1, w3, w2);   // 0
    router_kernel<<<NTOK, 256>>>(x, wr);                                  // 1
    offsets_scatter_kernel<<<1, 1024>>>();                                // 2
    gemm1_kernel<<<dim3(32, FDIM/128, NEXP), 256, G1_SMEM>>>();           // 3 <- profiled
    gemm2_kernel<<<dim3(32, CDIM/256, NEXP), 256, G2_SMEM>>>();           // 4
    combine_kernel<<<(NTOK * (CDIM/4)) / 256, 256>>>((float4*)out);       // 5
}

// round 16
// speedup vs baseline: 1.1327x; 1.0109x over previous
#include <cuda_runtime.h>
#include <math.h>
#include <stdint.h>

#if defined(__CUDA_ARCH__) && defined(__CUDA_ARCH_FEAT_SM103_ALL)
#define USE_TC 1
#else
#define USE_TC 0
#endif

#define NTOK 4096
#define CDIM 2048
#define FDIM 1024
#define NEXP 8
#define RPAD (2*NTOK + NEXP*128)   // 8704 padded permuted rows

// ---------------- device scratch ----------------
__device__ int   g_te[NTOK*2];
__device__ float g_tp[NTOK*2];
__device__ int   g_cnt[NEXP];
__device__ int   g_base[NEXP];
__device__ int   g_tok[RPAD];
__device__ float g_w[RPAD];
__device__ int   g_pos[NTOK*2];
__device__ float g_xt[(size_t)NTOK * CDIM];        // tf32-rounded x
__device__ float g_H[(size_t)RPAD * FDIM];
__device__ float g_O[(size_t)RPAD * CDIM];
__device__ float g_w1t[(size_t)NEXP*FDIM*CDIM];    // [E][F][C] K-major tf32
__device__ float g_w3t[(size_t)NEXP*FDIM*CDIM];
__device__ float g_w2t[(size_t)NEXP*CDIM*FDIM];    // [E][C][F] K-major tf32

// ---------------- helpers ----------------
__device__ __forceinline__ uint32_t smem_u32(const void* p) {
    uint32_t a;
    asm("{ .reg .u64 t; cvta.to.shared.u64 t, %1; cvt.u32.u64 %0, t; }" : "=r"(a) : "l"(p));
    return a;
}
__device__ __forceinline__ float to_tf32(float x) {
    float r; asm("cvt.rna.tf32.f32 %0, %1;" : "=f"(r) : "f"(x)); return r;
}

#if USE_TC
__device__ __forceinline__ uint32_t elect_one() {
    uint32_t p;
    asm volatile("{ .reg .pred p; elect.sync _|p, 0xFFFFFFFF; selp.b32 %0, 1, 0, p; }" : "=r"(p));
    return p;
}
__device__ __forceinline__ float fast_tanh(float x) {
    float r; asm("tanh.approx.f32 %0, %1;" : "=f"(r) : "f"(x)); return r;
}
#define MBAR_INIT(a, c) asm volatile("mbarrier.init.shared.b64 [%0], %1;" :: "r"(a), "r"(c) : "memory")
__device__ __forceinline__ void mbar_wait(uint32_t addr, uint32_t parity) {
    asm volatile(
        "{\n\t.reg .pred P;\n\t"
        "W_%=:\n\t"
        "mbarrier.try_wait.parity.acquire.cta.shared::cta.b64 P, [%0], %1, 0x989680;\n\t"
        "@P bra D_%=;\n\t"
        "bra W_%=;\n\t"
        "D_%=:\n\t}"
        :: "r"(addr), "r"(parity) : "memory");
}
#define TC_ALLOC(sa, n)   asm volatile("tcgen05.alloc.cta_group::1.sync.aligned.shared::cta.b32 [%0], %1;" :: "r"(sa), "r"(n) : "memory")
#define TC_DEALLOC(t, n)  asm volatile("tcgen05.dealloc.cta_group::1.sync.aligned.b32 %0, %1;" :: "r"(t), "r"(n))
#define TC_RELINQ()       asm volatile("tcgen05.relinquish_alloc_permit.cta_group::1.sync.aligned;")
#define TC_COMMIT(mb)     asm volatile("tcgen05.commit.cta_group::1.mbarrier::arrive::one.shared::cluster.b64 [%0];" :: "r"(mb) : "memory")
#define TC_FENCE_AFTER()  asm volatile("tcgen05.fence::after_thread_sync;" ::: "memory")
#define TC_FENCE_BEFORE() asm volatile("tcgen05.fence::before_thread_sync;" ::: "memory")
#define TC_WAIT_LD()      asm volatile("tcgen05.wait::ld.sync.aligned;" ::: "memory")
#define FENCE_ASYNC()     asm volatile("fence.proxy.async.shared::cta;" ::: "memory")

#define CP_ASYNC16(sm, gm) asm volatile("cp.async.cg.shared.global [%0], [%1], 16;" :: "r"(sm), "l"(gm) : "memory")
// .noinc is load-bearing (R13 deadlocked without it)
#define CP_MBAR_ARRIVE(mb) asm volatile("cp.async.mbarrier.arrive.noinc.shared::cta.b64 [%0];" :: "r"(mb) : "memory")

__device__ __forceinline__ void mma_tf32_ss(uint32_t d, uint64_t a, uint64_t b,
                                            uint32_t idesc, uint32_t acc) {
    asm volatile(
        "{\n\t.reg .pred p;\n\tsetp.ne.u32 p, %5, 0;\n\t"
        "tcgen05.mma.cta_group::1.kind::tf32 [%0], %1, %2, %3, {%4, %4, %4, %4}, p;\n\t}"
        :: "r"(d), "l"(a), "l"(b), "r"(idesc), "r"(0u), "r"(acc) : "memory");
}

#define TMEM_LD32(r, a) \
    asm volatile("tcgen05.ld.sync.aligned.32x32b.x32.b32 " \
        "{%0,%1,%2,%3,%4,%5,%6,%7,%8,%9,%10,%11,%12,%13,%14,%15," \
        "%16,%17,%18,%19,%20,%21,%22,%23,%24,%25,%26,%27,%28,%29,%30,%31}, [%32];" \
        : "=r"((r)[0]),"=r"((r)[1]),"=r"((r)[2]),"=r"((r)[3]),"=r"((r)[4]),"=r"((r)[5]),"=r"((r)[6]),"=r"((r)[7]), \
          "=r"((r)[8]),"=r"((r)[9]),"=r"((r)[10]),"=r"((r)[11]),"=r"((r)[12]),"=r"((r)[13]),"=r"((r)[14]),"=r"((r)[15]), \
          "=r"((r)[16]),"=r"((r)[17]),"=r"((r)[18]),"=r"((r)[19]),"=r"((r)[20]),"=r"((r)[21]),"=r"((r)[22]),"=r"((r)[23]), \
          "=r"((r)[24]),"=r"((r)[25]),"=r"((r)[26]),"=r"((r)[27]),"=r"((r)[28]),"=r"((r)[29]),"=r"((r)[30]),"=r"((r)[31]) \
        : "r"(a))

static __device__ __forceinline__ uint64_t make_desc(uint32_t addr) {
    const uint64_t base =
        (uint64_t(2) << 61) | (uint64_t(1) << 46) | (uint64_t(64) << 32) | (uint64_t(1) << 16);
    return base | ((uint64_t)(addr >> 4) & 0x3FFF);
}
#define SWZ(o) ((o) ^ (((o) >> 3) & 0x70))
#define IDESC_N256 (0x10u | (2u<<7) | (2u<<10) | ((256u/8u)<<17) | ((128u/16u)<<24))
#endif // USE_TC

// ---------------- prep: transposes (y=0..2) + xt/init (y=3) ----------------
__global__ __launch_bounds__(256) void prep_kernel(
    const float4* __restrict__ x4,
    const float* __restrict__ w1, const float* __restrict__ w3,
    const float* __restrict__ w2) {
    int which = blockIdx.y;
    if (which == 3) {
        int i = blockIdx.x * blockDim.x + threadIdx.x;
        float4 v = x4[i];
        v.x = to_tf32(v.x); v.y = to_tf32(v.y); v.z = to_tf32(v.z); v.w = to_tf32(v.w);
        ((float4*)g_xt)[i] = v;
        if (i < RPAD) g_tok[i] = -1;
        if (i < NEXP) g_cnt[i] = 0;
        return;
    }
    if (blockIdx.x >= 4096) return;
    __shared__ float ts[32][129];
    const float* in;
    float* out;
    int R, Cc;
    if (which == 0)      { in = w1; out = g_w1t; R = CDIM; Cc = FDIM; }
    else if (which == 1) { in = w3; out = g_w3t; R = CDIM; Cc = FDIM; }
    else                 { in = w2; out = g_w2t; R = FDIM; Cc = CDIM; }
    int nx = Cc / 128;
    int e = blockIdx.x / (nx * (R / 32));
    int rem = blockIdx.x % (nx * (R / 32));
    int cx = rem % nx, rx = rem / nx;
    size_t eoff = (size_t)e * R * Cc;
    int c0 = cx * 128;
    int r0 = rx * 32;
    int tx = threadIdx.x & 31, ty = threadIdx.x >> 5;
    #pragma unroll
    for (int j = ty; j < 32; j += 8) {
        float4 v = *(const float4*)(in + eoff + (size_t)(r0 + j) * Cc + c0 + tx * 4);
        ts[j][tx*4+0] = to_tf32(v.x);
        ts[j][tx*4+1] = to_tf32(v.y);
        ts[j][tx*4+2] = to_tf32(v.z);
        ts[j][tx*4+3] = to_tf32(v.w);
    }
    __syncthreads();
    int t = threadIdx.x;
    #pragma unroll
    for (int i = 0; i < 4; i++) {
        int idx = t + i * 256;
        int oc = idx >> 3;
        int q4 = idx & 7;
        float4 v;
        v.x = ts[q4*4+0][oc];
        v.y = ts[q4*4+1][oc];
        v.z = ts[q4*4+2][oc];
        v.w = ts[q4*4+3][oc];
        *(float4*)(out + eoff + (size_t)(c0 + oc) * R + r0 + q4 * 4) = v;
    }
}

// ---------------- router ----------------
__global__ void router_kernel(const float* __restrict__ x, const float* __restrict__ wr) {
    __shared__ float xs[CDIM];
    __shared__ float lg[NEXP];
    int t = blockIdx.x;
    const float4* xrow = (const float4*)(x + (size_t)t * CDIM);
    for (int i = threadIdx.x; i < CDIM / 4; i += blockDim.x)
        ((float4*)xs)[i] = xrow[i];
    __syncthreads();
    int warp = threadIdx.x >> 5, lane = threadIdx.x & 31;
    float s = 0.f;
    #pragma unroll 8
    for (int c = lane; c < CDIM; c += 32) s += xs[c] * wr[c * NEXP + warp];
    #pragma unroll
    for (int o = 16; o > 0; o >>= 1) s += __shfl_xor_sync(0xFFFFFFFFu, s, o);
    if (lane == 0) lg[warp] = s;
    __syncthreads();
    if (threadIdx.x == 0) {
        int i0 = 0; float v0 = lg[0];
        #pragma unroll
        for (int e = 1; e < NEXP; e++) if (lg[e] > v0) { v0 = lg[e]; i0 = e; }
        int i1 = -1; float v1 = -INFINITY;
        #pragma unroll
        for (int e = 0; e < NEXP; e++) if (e != i0 && lg[e] > v1) { v1 = lg[e]; i1 = e; }
        float e1 = __expf(v1 - v0);
        float inv = 1.f / (1.f + e1);
        g_te[t*2+0] = i0; g_tp[t*2+0] = inv;
        g_te[t*2+1] = i1; g_tp[t*2+1] = e1 * inv;
        atomicAdd(&g_cnt[i0], 1);
        atomicAdd(&g_cnt[i1], 1);
    }
}

// ---------------- offsets + scatter fused (single block) ----------------
__global__ __launch_bounds__(1024) void offsets_scatter_kernel() {
    __shared__ int s_fill[NEXP];
    if (threadIdx.x == 0) {
        int b = 0;
        #pragma unroll
        for (int e = 0; e < NEXP; e++) {
            g_base[e] = b;
            b += ((g_cnt[e] + 127) >> 7) << 7;
        }
    }
    if (threadIdx.x < NEXP) s_fill[threadIdx.x] = 0;
    __syncthreads();
    for (int t = threadIdx.x; t < NTOK; t += 1024) {
        #pragma unroll
        for (int k = 0; k < 2; k++) {
            int e = g_te[t*2+k];
            int pos = g_base[e] + atomicAdd(&s_fill[e], 1);
            g_tok[pos] = t;
            g_w[pos] = g_tp[t*2+k];
            g_pos[t*2+k] = pos;
        }
    }
}

// ==== GEMM1: warp-specialized (static producers), M=128 N=256, 2 CTAs/SM ====
// ctrl: +0 tmem, +16 full0(192), +24 full1(192), +32 done0(1), +40 done1(1), +48 fin(1)
#define G1_A(s)  ((s)*16384)
#define G1_B(s)  (32768 + (s)*32768)   // [B1 16K | B2 16K] contiguous
#define G1_CTRL  98304
#define G1_SMEM  (98304 + 64 + 1024 + 1024)

__global__ __launch_bounds__(256, 2) void gemm1_kernel() {
    int e = blockIdx.z;
    int cnt = g_cnt[e];
    int rt = blockIdx.x;
    if (rt * 128 >= cnt) return;
    int r0 = g_base[e] + rt * 128;
    int f0 = blockIdx.y * 128;
    int t = threadIdx.x;
    const float* b1base = g_w1t + ((size_t)e * FDIM + f0) * CDIM;
    const float* b2base = g_w3t + ((size_t)e * FDIM + f0) * CDIM;

#if USE_TC
    extern __shared__ char dynsmem[];
    uint32_t raw = smem_u32(dynsmem);
    uint32_t sbase = (raw + 1023) & ~1023u;
    char* smb = dynsmem + (sbase - raw);
    uint32_t ctrl = sbase + G1_CTRL;
    int*   s_tok = (int*)(smb + G1_CTRL + 64);
    float* s_w   = (float*)(smb + G1_CTRL + 576);

    int wid = t >> 5, lid = t & 31;
    if (wid == 0) { TC_ALLOC(ctrl, 256); TC_RELINQ(); }
    if (t < 128) {
        int tk = g_tok[r0 + t];
        s_tok[t] = tk < 0 ? 0 : tk;
        s_w[t]   = tk < 0 ? 0.f : g_w[r0 + t];
    }
    if (t == 0) {
        MBAR_INIT(ctrl + 16, 192); MBAR_INIT(ctrl + 24, 192);
        MBAR_INIT(ctrl + 32, 1);   MBAR_INIT(ctrl + 40, 1);
        MBAR_INIT(ctrl + 48, 1);
    }
    __syncthreads();
    uint32_t tmem;
    asm volatile("ld.shared.b32 %0, [%1];" : "=r"(tmem) : "r"(ctrl));

    const int NC = CDIM / 32;   // 64 chunks
    if (wid >= 2) {
        // ------- producers: warps 2-7 (192 threads), 16 static slots each -------
        int tp = t - 64;
        int phd0 = 0, phd1 = 0;
        for (int kc = 0; kc < NC; kc++) {
            int s = kc & 1;
            if (kc >= 2) {
                if (s == 0) { mbar_wait(ctrl + 32, phd0); phd0 ^= 1; }
                else        { mbar_wait(ctrl + 40, phd1); phd1 ^= 1; }
            }
            int k0 = kc * 32;
            #pragma unroll
            for (int i = 0; i < 16; i++) {
                int idx = tp + i * 192;            // 0..3071
                if (idx < 1024) {                   // A: 128 rows x 8 f4
                    int row = idx >> 3, c4 = idx & 7;
                    CP_ASYNC16(sbase + G1_A(s) + SWZ(row * 128 + c4 * 16),
                               g_xt + (size_t)s_tok[row] * CDIM + k0 + c4 * 4);
                } else {                            // B: 256 rows (w1|w3)
                    int sub = idx - 1024;
                    int row = sub >> 3, c4 = sub & 7;
                    const float* src = (row < 128)
                        ? b1base + (size_t)row * CDIM + k0 + c4 * 4
                        : b2base + (size_t)(row - 128) * CDIM + k0 + c4 * 4;
                    CP_ASYNC16(sbase + G1_B(s) + SWZ(row * 128 + c4 * 16), src);
                }
            }
            CP_MBAR_ARRIVE(ctrl + 16 + s * 8);
        }
    } else if (wid == 0) {
        // ------- consumer: warp 0 (MMA only) -------
        int phf0 = 0, phf1 = 0;
        for (int kc = 0; kc < NC; kc++) {
            int s = kc & 1;
            if (s == 0) { mbar_wait(ctrl + 16, phf0); phf0 ^= 1; }
            else        { mbar_wait(ctrl + 24, phf1); phf1 ^= 1; }
            if (elect_one()) {
                FENCE_ASYNC();
                uint64_t ad = make_desc(sbase + G1_A(s));
                uint64_t bd = make_desc(sbase + G1_B(s));
                #pragma unroll
                for (int j = 0; j < 4; j++) {
                    uint32_t acc = (kc > 0 || j > 0) ? 1u : 0u;
                    mma_tf32_ss(tmem, ad + j*2, bd + j*2, IDESC_N256, acc);
                }
                if (kc == NC - 1) TC_COMMIT(ctrl + 48);
                else              TC_COMMIT(ctrl + 32 + s * 8);
            }
        }
    }
    // all warps: wait final MMA completion
    mbar_wait(ctrl + 48, 0);
    TC_FENCE_AFTER();

    {   // 8-warp epilogue: D cols 0-127 = g, 128-255 = u
        int wq = wid & 3, half = wid >> 2;
        int m = wq * 32 + lid;
        float wgt = s_w[m];
        float* hrow = g_H + (size_t)(r0 + m) * FDIM + f0 + half * 64;
        #pragma unroll
        for (int base = 0; base < 64; base += 32) {
            uint32_t rg[32], ru[32];
            TMEM_LD32(rg, tmem + half * 64 + base);
            TMEM_LD32(ru, tmem + 128 + half * 64 + base);
            TC_WAIT_LD();
            #pragma unroll
            for (int j = 0; j < 32; j += 4) {
                float4 h4;
                float hv[4];
                #pragma unroll
                for (int q = 0; q < 4; q++) {
                    float g = __uint_as_float(rg[j+q]);
                    float u = __uint_as_float(ru[j+q]);
                    float sig = 0.5f * fast_tanh(0.5f * g) + 0.5f;
                    hv[q] = to_tf32(g * sig * u * wgt);
                }
                h4.x = hv[0]; h4.y = hv[1]; h4.z = hv[2]; h4.w = hv[3];
                *(float4*)(hrow + base + j) = h4;
            }
        }
        TC_FENCE_BEFORE();
    }
    __syncthreads();
    if (wid == 0) TC_DEALLOC(tmem, 256);
#else
    // FFMA fallback (compute_103 PTX insurance)
    int row = t & 127, half = t >> 7;
    int tk = g_tok[r0 + row];
    float wgt = tk < 0 ? 0.f : g_w[r0 + row];
    int mytok = tk < 0 ? 0 : tk;
    const float* xr = g_xt + (size_t)mytok * CDIM;
    for (int c = 0; c < 64; c++) {
        int col = half * 64 + c;
        const float* w1r = b1base + (size_t)col * CDIM;
        const float* w3r = b2base + (size_t)col * CDIM;
        float sg = 0.f, su = 0.f;
        for (int k = 0; k < CDIM; k += 4) {
            float4 xv = *(const float4*)(xr + k);
            float4 a = *(const float4*)(w1r + k);
            float4 b = *(const float4*)(w3r + k);
            sg += xv.x*a.x + xv.y*a.y + xv.z*a.z + xv.w*a.w;
            su += xv.x*b.x + xv.y*b.y + xv.z*b.z + xv.w*b.w;
        }
        g_H[(size_t)(r0 + row) * FDIM + f0 + col] = sg / (1.f + __expf(-sg)) * su * wgt;
    }
#endif
}

// ==== GEMM2: warp-specialized (static producers), M=128 N=256, 2 CTAs/SM ====
#define G2_A(s)  ((s)*16384)
#define G2_B(s)  (32768 + (s)*32768)
#define G2_CTRL  98304
#define G2_SMEM  (98304 + 64 + 1024)

__global__ __launch_bounds__(256, 2) void gemm2_kernel() {
    int e = blockIdx.z;
    int cnt = g_cnt[e];
    int rt = blockIdx.x;
    if (rt * 128 >= cnt) return;
    int r0 = g_base[e] + rt * 128;
    int c0 = blockIdx.y * 256;
    int t = threadIdx.x;
    const float* Bbase = g_w2t + ((size_t)e * CDIM + c0) * FDIM;

#if USE_TC
    extern __shared__ char dynsmem[];
    uint32_t raw = smem_u32(dynsmem);
    uint32_t sbase = (raw + 1023) & ~1023u;
    char* smb = dynsmem + (sbase - raw);
    (void)smb;
    uint32_t ctrl = sbase + G2_CTRL;

    int wid = t >> 5, lid = t & 31;
    if (wid == 0) { TC_ALLOC(ctrl, 256); TC_RELINQ(); }
    if (t == 0) {
        MBAR_INIT(ctrl + 16, 192); MBAR_INIT(ctrl + 24, 192);
        MBAR_INIT(ctrl + 32, 1);   MBAR_INIT(ctrl + 40, 1);
        MBAR_INIT(ctrl + 48, 1);
    }
    __syncthreads();
    uint32_t tmem;
    asm volatile("ld.shared.b32 %0, [%1];" : "=r"(tmem) : "r"(ctrl));

    const float* Abase = g_H + (size_t)r0 * FDIM;
    const int NC = FDIM / 32;   // 32 chunks

    if (wid >= 2) {
        int tp = t - 64;
        int phd0 = 0, phd1 = 0;
        for (int kc = 0; kc < NC; kc++) {
            int s = kc & 1;
            if (kc >= 2) {
                if (s == 0) { mbar_wait(ctrl + 32, phd0); phd0 ^= 1; }
                else        { mbar_wait(ctrl + 40, phd1); phd1 ^= 1; }
            }
            int k0 = kc * 32;
            #pragma unroll
            for (int i = 0; i < 16; i++) {
                int idx = tp + i * 192;
                if (idx < 1024) {
                    int row = idx >> 3, c4 = idx & 7;
                    CP_ASYNC16(sbase + G2_A(s) + SWZ(row * 128 + c4 * 16),
                               Abase + (size_t)row * FDIM + k0 + c4 * 4);
                } else {
                    int sub = idx - 1024;
                    int row = sub >> 3, c4 = sub & 7;
                    CP_ASYNC16(sbase + G2_B(s) + SWZ(row * 128 + c4 * 16),
                               Bbase + (size_t)row * FDIM + k0 + c4 * 4);
                }
            }
            CP_MBAR_ARRIVE(ctrl + 16 + s * 8);
        }
    } else if (wid == 0) {
        int phf0 = 0, phf1 = 0;
        for (int kc = 0; kc < NC; kc++) {
            int s = kc & 1;
            if (s == 0) { mbar_wait(ctrl + 16, phf0); phf0 ^= 1; }
            else        { mbar_wait(ctrl + 24, phf1); phf1 ^= 1; }
            if (elect_one()) {
                FENCE_ASYNC();
                uint64_t ad = make_desc(sbase + G2_A(s));
                uint64_t bd = make_desc(sbase + G2_B(s));
                #pragma unroll
                for (int j = 0; j < 4; j++) {
                    uint32_t acc = (kc > 0 || j > 0) ? 1u : 0u;
                    mma_tf32_ss(tmem, ad + j*2, bd + j*2, IDESC_N256, acc);
                }
                if (kc == NC - 1) TC_COMMIT(ctrl + 48);
                else              TC_COMMIT(ctrl + 32 + s * 8);
            }
        }
    }
    mbar_wait(ctrl + 48, 0);
    TC_FENCE_AFTER();

    {   // epilogue: 8 warps = (subpartition wid&3) x (column half wid>>2, 128 cols)
        int wq = wid & 3, half = wid >> 2;
        int m = wq * 32 + lid;
        float* orow = g_O + (size_t)(r0 + m) * CDIM + c0 + half * 128;
        #pragma unroll
        for (int base = 0; base < 128; base += 32) {
            uint32_t r[32];
            TMEM_LD32(r, tmem + half * 128 + base);
            TC_WAIT_LD();
            #pragma unroll
            for (int j = 0; j < 32; j += 4) {
                float4 v;
                v.x = __uint_as_float(r[j+0]);
                v.y = __uint_as_float(r[j+1]);
                v.z = __uint_as_float(r[j+2]);
                v.w = __uint_as_float(r[j+3]);
                *(float4*)(orow + base + j) = v;
            }
        }
        TC_FENCE_BEFORE();
    }
    __syncthreads();
    if (wid == 0) TC_DEALLOC(tmem, 256);
#else
    // FFMA fallback
    int row = t & 127, half = t >> 7;
    const float* hr = g_H + (size_t)(r0 + row) * FDIM;
    for (int c = 0; c < 128; c++) {
        int col = half * 128 + c;
        const float* w2r = Bbase + (size_t)col * FDIM;
        float sv = 0.f;
        for (int k = 0; k < FDIM; k += 4) {
            float4 hv = *(const float4*)(hr + k);
            float4 b = *(const float4*)(w2r + k);
            sv += hv.x*b.x + hv.y*b.y + hv.z*b.z + hv.w*b.w;
        }
        g_O[(size_t)(r0 + row) * CDIM + c0 + col] = sv;
    }
#endif
}

// ---------------- combine: out[t] = O[p0] + O[p1] ----------------
__global__ void combine_kernel(float4* __restrict__ out4) {
    int v = blockIdx.x * blockDim.x + threadIdx.x;
    int tk = v >> 9, c4 = v & 511;
    int p0 = g_pos[tk*2], p1 = g_pos[tk*2+1];
    const float4* O4 = (const float4*)g_O;
    float4 a = O4[(size_t)p0 * 512 + c4];
    float4 b = O4[(size_t)p1 * 512 + c4];
    out4[v] = make_float4(a.x + b.x, a.y + b.y, a.z + b.z, a.w + b.w);
}

// ---------------- launch ----------------
extern "C" void kernel_launch(void* const* d_in, const int* in_sizes, int n_in,
                              void* d_out, int out_size) {
    const float* x  = (const float*)d_in[0];
    const float* wr = (const float*)d_in[1];
    const float* w1 = (const float*)d_in[2];
    const float* w3 = (const float*)d_in[3];
    const float* w2 = (const float*)d_in[4];
    float* out = (float*)d_out;

    cudaFuncSetAttribute(gemm1_kernel, cudaFuncAttributeMaxDynamicSharedMemorySize, G1_SMEM);
    cudaFuncSetAttribute(gemm2_kernel, cudaFuncAttributeMaxDynamicSharedMemorySize, G2_SMEM);

    // profiled launch is index 3 (0-based) -> gemm1
    prep_kernel<<<dim3(8192, 4), 256>>>((const float4*)x, w1, w3, w2);   // 0
    router_kernel<<<NTOK, 256>>>(x, wr);                                  // 1
    offsets_scatter_kernel<<<1, 1024>>>();                                // 2
    gemm1_kernel<<<dim3(32, FDIM/128, NEXP), 256, G1_SMEM>>>();           // 3 <- profiled
    gemm2_kernel<<<dim3(32, CDIM/256, NEXP), 256, G2_SMEM>>>();           // 4
    combine_kernel<<<(NTOK * (CDIM/4)) / 256, 256>>>((float4*)out);       // 5
}